// round 1
// baseline (speedup 1.0000x reference)
#include <cuda_runtime.h>
#include <cuda_bf16.h>
#include <math.h>

#define D 128
#define NMAX 50048
#define EMAX 960000
#define SLOPE 0.01f

// ---------------- static device scratch (no allocations allowed) ----------------
__device__ float g_deg[NMAX];
__device__ float g_dg[NMAX];
__device__ float g_dinv[NMAX];
__device__ int   g_cnt[NMAX];
__device__ int   g_ptr[NMAX + 1];
__device__ int   g_cur[NMAX];
__device__ int   g_colS[EMAX];
__device__ float g_wG[EMAX];
__device__ float g_wS[EMAX];
__device__ float4 g_x1[NMAX * 32];
__device__ float4 g_x2[NMAX * 32];
__device__ float4 g_x3[NMAX * 32];
__device__ float4 g_s1[NMAX * 32];
__device__ float4 g_s2[NMAX * 32];
__device__ float4 g_s3[NMAX * 32];
__device__ float4 g_s4[NMAX * 32];
__device__ float4 g_hp[NMAX * 32];
__device__ float4 g_t [NMAX * 32];

// ---------------- helpers ----------------
__device__ __forceinline__ float lrelu(float v) { return v > 0.0f ? v : v * SLOPE; }
__device__ __forceinline__ float rlu(float v)   { return v > 0.0f ? v : 0.0f; }

__device__ __forceinline__ float wsum(float v) {
    #pragma unroll
    for (int o = 16; o > 0; o >>= 1) v += __shfl_xor_sync(0xffffffffu, v, o);
    return v;
}

__device__ __forceinline__ unsigned long long pack2(float x, float y) {
    unsigned long long r;
    asm("mov.b64 %0, {%1, %2};" : "=l"(r) : "f"(x), "f"(y));
    return r;
}
__device__ __forceinline__ unsigned long long dup2(float x) {
    unsigned long long r;
    asm("mov.b64 %0, {%1, %1};" : "=l"(r) : "f"(x));
    return r;
}
__device__ __forceinline__ void fma2(unsigned long long &d, unsigned long long a, unsigned long long b) {
    asm("fma.rn.f32x2 %0, %1, %2, %0;" : "+l"(d) : "l"(a), "l"(b));
}
__device__ __forceinline__ float2 unpack2(unsigned long long v) {
    float2 r;
    asm("mov.b64 {%0, %1}, %2;" : "=f"(r.x), "=f"(r.y) : "l"(v));
    return r;
}

// ---------------- setup kernels ----------------
__global__ void k_deg(const int* __restrict__ row, const int* __restrict__ col,
                      const float* __restrict__ w, int E) {
    int e = blockIdx.x * blockDim.x + threadIdx.x;
    if (e >= E) return;
    atomicAdd(&g_deg[col[e]], w[e]);
    atomicAdd(&g_cnt[row[e]], 1);
}

__global__ void k_scale(int N) {
    int i = blockIdx.x * blockDim.x + threadIdx.x;
    if (i >= N) return;
    float d = g_deg[i];
    g_dg[i]   = rsqrtf(d + 1.0f);
    g_dinv[i] = 1.0f / d;
}

// single-block chunked exclusive scan of g_cnt -> g_ptr
__global__ void k_scan(int N) {
    __shared__ int sdata[1024];
    __shared__ int carry;
    int tid = threadIdx.x;
    if (tid == 0) carry = 0;
    __syncthreads();
    for (int base = 0; base < N; base += 1024) {
        int i = base + tid;
        int v = (i < N) ? g_cnt[i] : 0;
        sdata[tid] = v;
        __syncthreads();
        #pragma unroll
        for (int off = 1; off < 1024; off <<= 1) {
            int t = (tid >= off) ? sdata[tid - off] : 0;
            __syncthreads();
            sdata[tid] += t;
            __syncthreads();
        }
        int c = carry;
        if (i < N) g_ptr[i] = c + sdata[tid] - v;
        int total = sdata[1023];
        __syncthreads();
        if (tid == 0) carry = c + total;
        __syncthreads();
    }
    if (tid == 0) g_ptr[N] = carry;
}

__global__ void k_scatter(const int* __restrict__ row, const int* __restrict__ col,
                          const float* __restrict__ w, int E) {
    int e = blockIdx.x * blockDim.x + threadIdx.x;
    if (e >= E) return;
    int r = row[e], c = col[e];
    int pos = g_ptr[r] + atomicAdd(&g_cur[r], 1);
    float wv = w[e];
    g_colS[pos] = c;
    g_wG[pos]   = wv * g_dg[c];
    g_wS[pos]   = wv * g_dinv[c];
}

// ---------------- SPMM kernels (one warp per node) ----------------
__global__ void k_spmm_gcn(const float4* __restrict__ xin, float4* __restrict__ xout, int N) {
    int gt = blockIdx.x * blockDim.x + threadIdx.x;
    int wid = gt >> 5, lane = gt & 31;
    if (wid >= N) return;
    int s = g_ptr[wid], e = g_ptr[wid + 1];
    float4 acc = make_float4(0.f, 0.f, 0.f, 0.f);
    int j = s;
    for (; j + 4 <= e; j += 4) {
        int c0 = g_colS[j], c1 = g_colS[j+1], c2 = g_colS[j+2], c3 = g_colS[j+3];
        float w0 = g_wG[j], w1 = g_wG[j+1], w2 = g_wG[j+2], w3 = g_wG[j+3];
        float4 v0 = __ldg(&xin[c0*32 + lane]);
        float4 v1 = __ldg(&xin[c1*32 + lane]);
        float4 v2 = __ldg(&xin[c2*32 + lane]);
        float4 v3 = __ldg(&xin[c3*32 + lane]);
        acc.x += w0*v0.x + w1*v1.x + w2*v2.x + w3*v3.x;
        acc.y += w0*v0.y + w1*v1.y + w2*v2.y + w3*v3.y;
        acc.z += w0*v0.z + w1*v1.z + w2*v2.z + w3*v3.z;
        acc.w += w0*v0.w + w1*v1.w + w2*v2.w + w3*v3.w;
    }
    for (; j < e; j++) {
        int c = g_colS[j]; float wv = g_wG[j];
        float4 v = __ldg(&xin[c*32 + lane]);
        acc.x += wv*v.x; acc.y += wv*v.y; acc.z += wv*v.z; acc.w += wv*v.w;
    }
    float dg = g_dg[wid];
    float4 xs = xin[wid*32 + lane];
    float4 r;
    r.x = (acc.x + xs.x*dg) * dg;
    r.y = (acc.y + xs.y*dg) * dg;
    r.z = (acc.z + xs.z*dg) * dg;
    r.w = (acc.w + xs.w*dg) * dg;
    xout[wid*32 + lane] = r;
}

__global__ void k_spmm_sct(const float4* __restrict__ xin, float4* __restrict__ xout, int N) {
    int gt = blockIdx.x * blockDim.x + threadIdx.x;
    int wid = gt >> 5, lane = gt & 31;
    if (wid >= N) return;
    int s = g_ptr[wid], e = g_ptr[wid + 1];
    float4 acc = make_float4(0.f, 0.f, 0.f, 0.f);
    int j = s;
    for (; j + 4 <= e; j += 4) {
        int c0 = g_colS[j], c1 = g_colS[j+1], c2 = g_colS[j+2], c3 = g_colS[j+3];
        float w0 = g_wS[j], w1 = g_wS[j+1], w2 = g_wS[j+2], w3 = g_wS[j+3];
        float4 v0 = __ldg(&xin[c0*32 + lane]);
        float4 v1 = __ldg(&xin[c1*32 + lane]);
        float4 v2 = __ldg(&xin[c2*32 + lane]);
        float4 v3 = __ldg(&xin[c3*32 + lane]);
        acc.x += w0*v0.x + w1*v1.x + w2*v2.x + w3*v3.x;
        acc.y += w0*v0.y + w1*v1.y + w2*v2.y + w3*v3.y;
        acc.z += w0*v0.z + w1*v1.z + w2*v2.z + w3*v3.z;
        acc.w += w0*v0.w + w1*v1.w + w2*v2.w + w3*v3.w;
    }
    for (; j < e; j++) {
        int c = g_colS[j]; float wv = g_wS[j];
        float4 v = __ldg(&xin[c*32 + lane]);
        acc.x += wv*v.x; acc.y += wv*v.y; acc.z += wv*v.z; acc.w += wv*v.w;
    }
    float4 xs = xin[wid*32 + lane];
    float4 r;
    r.x = 0.5f*xs.x + 0.5f*acc.x;
    r.y = 0.5f*xs.y + 0.5f*acc.y;
    r.z = 0.5f*xs.z + 0.5f*acc.z;
    r.w = 0.5f*xs.w + 0.5f*acc.w;
    xout[wid*32 + lane] = r;
}

// ---------------- attention + combine (one warp per node) ----------------
__device__ __forceinline__ float4 lrelu4(float4 v) {
    return make_float4(lrelu(v.x), lrelu(v.y), lrelu(v.z), lrelu(v.w));
}
__device__ __forceinline__ float apw(float d, bool is1, float mf) {
    float a = fabsf(d);
    return is1 ? a : __powf(a, mf);
}

__global__ void k_attn(const float4* __restrict__ X, const float4* __restrict__ a4,
                       const int* __restrict__ mom, float4* __restrict__ hp, int N) {
    int gt = blockIdx.x * blockDim.x + threadIdx.x;
    int wid = gt >> 5, lane = gt & 31;
    if (wid >= N) return;
    float4 aX = a4[lane];
    float4 aH = a4[32 + lane];
    int base = wid*32 + lane;

    float4 xr = X[base];
    float eX = wsum(rlu(xr.x)*aX.x + rlu(xr.y)*aX.y + rlu(xr.z)*aX.z + rlu(xr.w)*aX.w);

    int mi = mom[0];
    bool is1 = (mi == 1) || (__int_as_float(mi) == 1.0f);
    float mf = 1.0f;
    if (!is1) mf = (mi > 0 && mi < 64) ? (float)mi : __int_as_float(mi);

    float4 h[6];
    h[0] = lrelu4(g_x1[base]);
    h[1] = lrelu4(g_x2[base]);
    h[2] = lrelu4(g_x3[base]);
    float4 p1 = g_s1[base], p2 = g_s2[base], p3 = g_s3[base], p4 = g_s4[base];
    h[3] = make_float4(apw(p1.x-p2.x,is1,mf), apw(p1.y-p2.y,is1,mf), apw(p1.z-p2.z,is1,mf), apw(p1.w-p2.w,is1,mf));
    h[4] = make_float4(apw(p2.x-p3.x,is1,mf), apw(p2.y-p3.y,is1,mf), apw(p2.z-p3.z,is1,mf), apw(p2.w-p3.w,is1,mf));
    h[5] = make_float4(apw(p3.x-p4.x,is1,mf), apw(p3.y-p4.y,is1,mf), apw(p3.z-p4.z,is1,mf), apw(p3.w-p4.w,is1,mf));

    float e[6];
    #pragma unroll
    for (int c = 0; c < 6; c++) {
        float part = rlu(h[c].x)*aH.x + rlu(h[c].y)*aH.y + rlu(h[c].z)*aH.z + rlu(h[c].w)*aH.w;
        e[c] = eX + wsum(part);
    }
    float mx = e[0];
    #pragma unroll
    for (int c = 1; c < 6; c++) mx = fmaxf(mx, e[c]);
    float at[6], s = 0.f;
    #pragma unroll
    for (int c = 0; c < 6; c++) { at[c] = __expf(e[c] - mx); s += at[c]; }
    float inv = 1.0f / (6.0f * s);
    float4 o = make_float4(0.f, 0.f, 0.f, 0.f);
    #pragma unroll
    for (int c = 0; c < 6; c++) {
        o.x += at[c]*h[c].x; o.y += at[c]*h[c].y; o.z += at[c]*h[c].z; o.w += at[c]*h[c].w;
    }
    o.x *= inv; o.y *= inv; o.z *= inv; o.w *= inv;
    hp[base] = o;
}

// ---------------- fused GEMM + leaky-relu: out[n,o] = lrelu(sum_k A[n,k]*W[o,k] + b[o]) ----------------
// block = 256 threads, 128-row tile per block, f32x2 packed FMA,
// transposed W in smem (conflict-free via 32x33 staging tile).
extern __shared__ float dsm[];
__global__ __launch_bounds__(256, 1)
void k_gemm(const float* __restrict__ A, const float* __restrict__ W,
            const float* __restrict__ bias, float* __restrict__ out, int N) {
    float* Wt = dsm;            // 16384 floats: Wt[k*128 + o]
    float* hs = dsm + 16384;    // 16384 floats: 128 rows x 128
    __shared__ float stage[32][33];

    int tid = threadIdx.x;
    int tx = tid & 31, ty0 = tid >> 5;
    int row0 = blockIdx.x * 128;

    // load row tile (float4, coalesced, zero-pad OOB)
    {
        const float4* A4 = (const float4*)(A + (size_t)row0 * D);
        float4* hs4 = (float4*)hs;
        float4 z = make_float4(0.f, 0.f, 0.f, 0.f);
        #pragma unroll
        for (int i = tid; i < 4096; i += 256) {
            int r = row0 + (i >> 5);
            hs4[i] = (r < N) ? A4[i] : z;
        }
    }
    // transpose W into Wt (both smem sides conflict-free)
    for (int t = 0; t < 16; t++) {
        int ko = (t >> 2) << 5, oo = (t & 3) << 5;
        #pragma unroll
        for (int i = 0; i < 4; i++) {
            int ty = ty0 + i * 8;
            stage[ty][tx] = W[(oo + ty) * D + ko + tx];
        }
        __syncthreads();
        #pragma unroll
        for (int i = 0; i < 4; i++) {
            int ty = ty0 + i * 8;
            Wt[(ko + ty) * D + oo + tx] = stage[tx][ty];
        }
        __syncthreads();
    }

    int wid = tid >> 5, lane = tid & 31;
    int o4 = lane << 2;
    unsigned long long acc[16][2];
    #pragma unroll
    for (int r = 0; r < 16; r++) { acc[r][0] = 0ull; acc[r][1] = 0ull; }

    for (int k4 = 0; k4 < 32; k4++) {
        unsigned long long wp[4][2];
        #pragma unroll
        for (int kk = 0; kk < 4; kk++) {
            float4 wv = *(const float4*)&Wt[(k4 * 4 + kk) * D + o4];
            wp[kk][0] = pack2(wv.x, wv.y);
            wp[kk][1] = pack2(wv.z, wv.w);
        }
        #pragma unroll
        for (int r = 0; r < 16; r++) {
            float4 h4 = *(const float4*)&hs[(wid * 16 + r) * D + k4 * 4];
            unsigned long long hp;
            hp = dup2(h4.x); fma2(acc[r][0], hp, wp[0][0]); fma2(acc[r][1], hp, wp[0][1]);
            hp = dup2(h4.y); fma2(acc[r][0], hp, wp[1][0]); fma2(acc[r][1], hp, wp[1][1]);
            hp = dup2(h4.z); fma2(acc[r][0], hp, wp[2][0]); fma2(acc[r][1], hp, wp[2][1]);
            hp = dup2(h4.w); fma2(acc[r][0], hp, wp[3][0]); fma2(acc[r][1], hp, wp[3][1]);
        }
    }

    float4 b4 = *(const float4*)&bias[o4];
    #pragma unroll
    for (int r = 0; r < 16; r++) {
        int rr = row0 + wid * 16 + r;
        if (rr < N) {
            float2 lo = unpack2(acc[r][0]);
            float2 hi = unpack2(acc[r][1]);
            float4 o;
            o.x = lrelu(lo.x + b4.x);
            o.y = lrelu(lo.y + b4.y);
            o.z = lrelu(hi.x + b4.z);
            o.w = lrelu(hi.y + b4.w);
            *(float4*)&out[(size_t)rr * D + o4] = o;
        }
    }
}

// ---------------- launch ----------------
extern "C" void kernel_launch(void* const* d_in, const int* in_sizes, int n_in,
                              void* d_out, int out_size) {
    const float* X   = (const float*)d_in[0];
    const int*   ei  = (const int*)d_in[1];
    const float* ew  = (const float*)d_in[2];
    const float* W1  = (const float*)d_in[3];
    const float* b1  = (const float*)d_in[4];
    const float* W2  = (const float*)d_in[5];
    const float* b2  = (const float*)d_in[6];
    const float* av  = (const float*)d_in[7];
    const int*   mom = (const int*)d_in[8];

    int N = in_sizes[0] / D;
    int E = in_sizes[2];
    const int* row = ei;
    const int* col = ei + E;

    void *p_deg, *p_cnt, *p_cur, *p_x1, *p_x2, *p_x3, *p_s1, *p_s2, *p_s3, *p_s4, *p_hp, *p_t;
    cudaGetSymbolAddress(&p_deg, g_deg);
    cudaGetSymbolAddress(&p_cnt, g_cnt);
    cudaGetSymbolAddress(&p_cur, g_cur);
    cudaGetSymbolAddress(&p_x1, g_x1);
    cudaGetSymbolAddress(&p_x2, g_x2);
    cudaGetSymbolAddress(&p_x3, g_x3);
    cudaGetSymbolAddress(&p_s1, g_s1);
    cudaGetSymbolAddress(&p_s2, g_s2);
    cudaGetSymbolAddress(&p_s3, g_s3);
    cudaGetSymbolAddress(&p_s4, g_s4);
    cudaGetSymbolAddress(&p_hp, g_hp);
    cudaGetSymbolAddress(&p_t,  g_t);

    cudaMemsetAsync(p_deg, 0, N * sizeof(float), 0);
    cudaMemsetAsync(p_cnt, 0, N * sizeof(int), 0);
    cudaMemsetAsync(p_cur, 0, N * sizeof(int), 0);

    int eb = (E + 255) / 256;
    int nb = (N + 255) / 256;
    int wb = (N * 32 + 255) / 256;

    k_deg<<<eb, 256>>>(row, col, ew, E);
    k_scale<<<nb, 256>>>(N);
    k_scan<<<1, 1024>>>(N);
    k_scatter<<<eb, 256>>>(row, col, ew, E);

    k_spmm_gcn<<<wb, 256>>>((const float4*)X,  (float4*)p_x1, N);
    k_spmm_gcn<<<wb, 256>>>((const float4*)p_x1, (float4*)p_x2, N);
    k_spmm_gcn<<<wb, 256>>>((const float4*)p_x2, (float4*)p_x3, N);

    k_spmm_sct<<<wb, 256>>>((const float4*)X,  (float4*)p_s1, N);
    k_spmm_sct<<<wb, 256>>>((const float4*)p_s1, (float4*)p_s2, N);
    k_spmm_sct<<<wb, 256>>>((const float4*)p_s2, (float4*)p_s3, N);
    k_spmm_sct<<<wb, 256>>>((const float4*)p_s3, (float4*)p_s4, N);

    k_attn<<<wb, 256>>>((const float4*)X, (const float4*)av, mom, (float4*)p_hp, N);

    cudaFuncSetAttribute(k_gemm, cudaFuncAttributeMaxDynamicSharedMemorySize, 131072);
    int gb = (N + 127) / 128;
    k_gemm<<<gb, 256, 131072>>>((const float*)p_hp, W1, b1, (float*)p_t, N);
    k_gemm<<<gb, 256, 131072>>>((const float*)p_t,  W2, b2, (float*)d_out, N);
}

// round 2
// speedup vs baseline: 1.0974x; 1.0974x over previous
#include <cuda_runtime.h>
#include <cuda_bf16.h>
#include <math.h>

#define D 128
#define NMAX 50048
#define EMAX 960000
#define SLOPE 0.01f

// ---------------- static device scratch (no allocations allowed) ----------------
__device__ float g_deg[NMAX];
__device__ float g_dg[NMAX];
__device__ float g_dinv[NMAX];
__device__ int   g_cnt[NMAX];
__device__ int   g_ptr[NMAX + 1];
__device__ int   g_cur[NMAX];
__device__ int   g_bsum[1024];
__device__ int   g_colS[EMAX];
__device__ float g_wG[EMAX];
__device__ float g_wS[EMAX];
__device__ float4 g_x1[NMAX * 32];
__device__ float4 g_x2[NMAX * 32];
__device__ float4 g_x3[NMAX * 32];
__device__ float4 g_s1[NMAX * 32];
__device__ float4 g_s2[NMAX * 32];
__device__ float4 g_s3[NMAX * 32];
__device__ float4 g_s4[NMAX * 32];

// ---------------- helpers ----------------
__device__ __forceinline__ float lrelu(float v) { return v > 0.0f ? v : v * SLOPE; }
__device__ __forceinline__ float rlu(float v)   { return v > 0.0f ? v : 0.0f; }

__device__ __forceinline__ float wsum(float v) {
    #pragma unroll
    for (int o = 16; o > 0; o >>= 1) v += __shfl_xor_sync(0xffffffffu, v, o);
    return v;
}

__device__ __forceinline__ unsigned long long pack2(float x, float y) {
    unsigned long long r;
    asm("mov.b64 %0, {%1, %2};" : "=l"(r) : "f"(x), "f"(y));
    return r;
}
__device__ __forceinline__ unsigned long long dup2(float x) {
    unsigned long long r;
    asm("mov.b64 %0, {%1, %1};" : "=l"(r) : "f"(x));
    return r;
}
__device__ __forceinline__ void fma2(unsigned long long &d, unsigned long long a, unsigned long long b) {
    asm("fma.rn.f32x2 %0, %1, %2, %0;" : "+l"(d) : "l"(a), "l"(b));
}
__device__ __forceinline__ float2 unpack2(unsigned long long v) {
    float2 r;
    asm("mov.b64 {%0, %1}, %2;" : "=f"(r.x), "=f"(r.y) : "l"(v));
    return r;
}

// ---------------- setup kernels ----------------
__global__ void k_deg(const int* __restrict__ row, const int* __restrict__ col,
                      const float* __restrict__ w, int E) {
    int e = blockIdx.x * blockDim.x + threadIdx.x;
    if (e >= E) return;
    atomicAdd(&g_deg[col[e]], w[e]);
    atomicAdd(&g_cnt[row[e]], 1);
}

__global__ void k_scale(int N) {
    int i = blockIdx.x * blockDim.x + threadIdx.x;
    if (i >= N) return;
    float d = g_deg[i];
    g_dg[i]   = rsqrtf(d + 1.0f);
    g_dinv[i] = 1.0f / d;
}

// 2-level scan: per-block exclusive scan + block sums
__global__ void k_scan1(int N) {
    __shared__ int sd[512];
    int tid = threadIdx.x;
    int i = blockIdx.x * 512 + tid;
    int v = (i < N) ? g_cnt[i] : 0;
    sd[tid] = v;
    __syncthreads();
    #pragma unroll
    for (int off = 1; off < 512; off <<= 1) {
        int t = (tid >= off) ? sd[tid - off] : 0;
        __syncthreads();
        sd[tid] += t;
        __syncthreads();
    }
    if (i < N) g_ptr[i] = sd[tid] - v;
    if (tid == 511) g_bsum[blockIdx.x] = sd[511];
}

__global__ void k_scan2(int nb, int N) {
    __shared__ int sd[1024];
    int tid = threadIdx.x;
    int v = (tid < nb) ? g_bsum[tid] : 0;
    sd[tid] = v;
    __syncthreads();
    #pragma unroll
    for (int off = 1; off < 1024; off <<= 1) {
        int t = (tid >= off) ? sd[tid - off] : 0;
        __syncthreads();
        sd[tid] += t;
        __syncthreads();
    }
    if (tid < nb) g_bsum[tid] = sd[tid] - v;
    if (tid == nb - 1) g_ptr[N] = sd[tid];
}

__global__ void k_scan3(int N) {
    int i = blockIdx.x * blockDim.x + threadIdx.x;
    if (i < N) g_ptr[i] += g_bsum[i >> 9];
}

__global__ void k_scatter(const int* __restrict__ row, const int* __restrict__ col,
                          const float* __restrict__ w, int E) {
    int e = blockIdx.x * blockDim.x + threadIdx.x;
    if (e >= E) return;
    int r = row[e], c = col[e];
    int pos = g_ptr[r] + atomicAdd(&g_cur[r], 1);
    float wv = w[e];
    g_colS[pos] = c;
    g_wG[pos]   = wv * g_dg[c];
    g_wS[pos]   = wv * g_dinv[c];
}

// ---------------- SPMM kernels (one warp per node) ----------------
// Layer 1: fused GCN+SCT sharing a single gather of X.
__global__ void k_spmm_first(const float4* __restrict__ X,
                             float4* __restrict__ x1, float4* __restrict__ s1, int N) {
    int gt = blockIdx.x * blockDim.x + threadIdx.x;
    int wid = gt >> 5, lane = gt & 31;
    if (wid >= N) return;
    int s = g_ptr[wid], e = g_ptr[wid + 1];
    float4 aG = make_float4(0.f,0.f,0.f,0.f);
    float4 aS = make_float4(0.f,0.f,0.f,0.f);
    int j = s;
    for (; j + 4 <= e; j += 4) {
        int c0 = g_colS[j], c1 = g_colS[j+1], c2 = g_colS[j+2], c3 = g_colS[j+3];
        float4 v0 = __ldg(&X[c0*32 + lane]);
        float4 v1 = __ldg(&X[c1*32 + lane]);
        float4 v2 = __ldg(&X[c2*32 + lane]);
        float4 v3 = __ldg(&X[c3*32 + lane]);
        float g0 = g_wG[j], g1 = g_wG[j+1], g2 = g_wG[j+2], g3 = g_wG[j+3];
        float q0 = g_wS[j], q1 = g_wS[j+1], q2 = g_wS[j+2], q3 = g_wS[j+3];
        aG.x += g0*v0.x + g1*v1.x + g2*v2.x + g3*v3.x;
        aG.y += g0*v0.y + g1*v1.y + g2*v2.y + g3*v3.y;
        aG.z += g0*v0.z + g1*v1.z + g2*v2.z + g3*v3.z;
        aG.w += g0*v0.w + g1*v1.w + g2*v2.w + g3*v3.w;
        aS.x += q0*v0.x + q1*v1.x + q2*v2.x + q3*v3.x;
        aS.y += q0*v0.y + q1*v1.y + q2*v2.y + q3*v3.y;
        aS.z += q0*v0.z + q1*v1.z + q2*v2.z + q3*v3.z;
        aS.w += q0*v0.w + q1*v1.w + q2*v2.w + q3*v3.w;
    }
    for (; j < e; j++) {
        int c = g_colS[j];
        float4 v = __ldg(&X[c*32 + lane]);
        float gw = g_wG[j], qw = g_wS[j];
        aG.x += gw*v.x; aG.y += gw*v.y; aG.z += gw*v.z; aG.w += gw*v.w;
        aS.x += qw*v.x; aS.y += qw*v.y; aS.z += qw*v.z; aS.w += qw*v.w;
    }
    float dg = g_dg[wid];
    float4 xs = X[wid*32 + lane];
    float4 rg, rs;
    rg.x = (aG.x + xs.x*dg) * dg; rg.y = (aG.y + xs.y*dg) * dg;
    rg.z = (aG.z + xs.z*dg) * dg; rg.w = (aG.w + xs.w*dg) * dg;
    rs.x = 0.5f*xs.x + 0.5f*aS.x; rs.y = 0.5f*xs.y + 0.5f*aS.y;
    rs.z = 0.5f*xs.z + 0.5f*aS.z; rs.w = 0.5f*xs.w + 0.5f*aS.w;
    x1[wid*32 + lane] = rg;
    s1[wid*32 + lane] = rs;
}

// Paired layer: GCN on xa (weights wG), SCT on xb (weights wS); shared indices.
__global__ void k_spmm_pair(const float4* __restrict__ xa, const float4* __restrict__ xb,
                            float4* __restrict__ oa, float4* __restrict__ ob, int N) {
    int gt = blockIdx.x * blockDim.x + threadIdx.x;
    int wid = gt >> 5, lane = gt & 31;
    if (wid >= N) return;
    int s = g_ptr[wid], e = g_ptr[wid + 1];
    float4 aG = make_float4(0.f,0.f,0.f,0.f);
    float4 aS = make_float4(0.f,0.f,0.f,0.f);
    int j = s;
    for (; j + 4 <= e; j += 4) {
        int c0 = g_colS[j], c1 = g_colS[j+1], c2 = g_colS[j+2], c3 = g_colS[j+3];
        float4 u0 = __ldg(&xa[c0*32 + lane]);
        float4 u1 = __ldg(&xa[c1*32 + lane]);
        float4 u2 = __ldg(&xa[c2*32 + lane]);
        float4 u3 = __ldg(&xa[c3*32 + lane]);
        float4 v0 = __ldg(&xb[c0*32 + lane]);
        float4 v1 = __ldg(&xb[c1*32 + lane]);
        float4 v2 = __ldg(&xb[c2*32 + lane]);
        float4 v3 = __ldg(&xb[c3*32 + lane]);
        float g0 = g_wG[j], g1 = g_wG[j+1], g2 = g_wG[j+2], g3 = g_wG[j+3];
        float q0 = g_wS[j], q1 = g_wS[j+1], q2 = g_wS[j+2], q3 = g_wS[j+3];
        aG.x += g0*u0.x + g1*u1.x + g2*u2.x + g3*u3.x;
        aG.y += g0*u0.y + g1*u1.y + g2*u2.y + g3*u3.y;
        aG.z += g0*u0.z + g1*u1.z + g2*u2.z + g3*u3.z;
        aG.w += g0*u0.w + g1*u1.w + g2*u2.w + g3*u3.w;
        aS.x += q0*v0.x + q1*v1.x + q2*v2.x + q3*v3.x;
        aS.y += q0*v0.y + q1*v1.y + q2*v2.y + q3*v3.y;
        aS.z += q0*v0.z + q1*v1.z + q2*v2.z + q3*v3.z;
        aS.w += q0*v0.w + q1*v1.w + q2*v2.w + q3*v3.w;
    }
    for (; j < e; j++) {
        int c = g_colS[j];
        float4 u = __ldg(&xa[c*32 + lane]);
        float4 v = __ldg(&xb[c*32 + lane]);
        float gw = g_wG[j], qw = g_wS[j];
        aG.x += gw*u.x; aG.y += gw*u.y; aG.z += gw*u.z; aG.w += gw*u.w;
        aS.x += qw*v.x; aS.y += qw*v.y; aS.z += qw*v.z; aS.w += qw*v.w;
    }
    float dg = g_dg[wid];
    float4 xg = xa[wid*32 + lane];
    float4 xs = xb[wid*32 + lane];
    float4 rg, rs;
    rg.x = (aG.x + xg.x*dg) * dg; rg.y = (aG.y + xg.y*dg) * dg;
    rg.z = (aG.z + xg.z*dg) * dg; rg.w = (aG.w + xg.w*dg) * dg;
    rs.x = 0.5f*xs.x + 0.5f*aS.x; rs.y = 0.5f*xs.y + 0.5f*aS.y;
    rs.z = 0.5f*xs.z + 0.5f*aS.z; rs.w = 0.5f*xs.w + 0.5f*aS.w;
    oa[wid*32 + lane] = rg;
    ob[wid*32 + lane] = rs;
}

__global__ void k_spmm_sct(const float4* __restrict__ xin, float4* __restrict__ xout, int N) {
    int gt = blockIdx.x * blockDim.x + threadIdx.x;
    int wid = gt >> 5, lane = gt & 31;
    if (wid >= N) return;
    int s = g_ptr[wid], e = g_ptr[wid + 1];
    float4 acc = make_float4(0.f, 0.f, 0.f, 0.f);
    int j = s;
    for (; j + 4 <= e; j += 4) {
        int c0 = g_colS[j], c1 = g_colS[j+1], c2 = g_colS[j+2], c3 = g_colS[j+3];
        float w0 = g_wS[j], w1 = g_wS[j+1], w2 = g_wS[j+2], w3 = g_wS[j+3];
        float4 v0 = __ldg(&xin[c0*32 + lane]);
        float4 v1 = __ldg(&xin[c1*32 + lane]);
        float4 v2 = __ldg(&xin[c2*32 + lane]);
        float4 v3 = __ldg(&xin[c3*32 + lane]);
        acc.x += w0*v0.x + w1*v1.x + w2*v2.x + w3*v3.x;
        acc.y += w0*v0.y + w1*v1.y + w2*v2.y + w3*v3.y;
        acc.z += w0*v0.z + w1*v1.z + w2*v2.z + w3*v3.z;
        acc.w += w0*v0.w + w1*v1.w + w2*v2.w + w3*v3.w;
    }
    for (; j < e; j++) {
        int c = g_colS[j]; float wv = g_wS[j];
        float4 v = __ldg(&xin[c*32 + lane]);
        acc.x += wv*v.x; acc.y += wv*v.y; acc.z += wv*v.z; acc.w += wv*v.w;
    }
    float4 xs = xin[wid*32 + lane];
    float4 r;
    r.x = 0.5f*xs.x + 0.5f*acc.x;
    r.y = 0.5f*xs.y + 0.5f*acc.y;
    r.z = 0.5f*xs.z + 0.5f*acc.z;
    r.w = 0.5f*xs.w + 0.5f*acc.w;
    xout[wid*32 + lane] = r;
}

// ---------------- fused epilogue: attention + GEMM1 + GEMM2 ----------------
__device__ __forceinline__ float4 lrelu4(float4 v) {
    return make_float4(lrelu(v.x), lrelu(v.y), lrelu(v.z), lrelu(v.w));
}
__device__ __forceinline__ float apw(float d, bool is1, float mf) {
    float a = fabsf(d);
    return is1 ? a : __powf(a, mf);
}

// conflict-free transpose of W [128x128] row-major into Wt[k*128+o]
__device__ __forceinline__ void wtrans(const float* __restrict__ W, float* Wt,
                                       float stage[32][33], int tid) {
    int tx = tid & 31, ty0 = tid >> 5;
    for (int t = 0; t < 16; t++) {
        int ko = (t >> 2) << 5, oo = (t & 3) << 5;
        #pragma unroll
        for (int i = 0; i < 4; i++) {
            int ty = ty0 + i * 8;
            stage[ty][tx] = W[(oo + ty) * D + ko + tx];
        }
        __syncthreads();
        #pragma unroll
        for (int i = 0; i < 4; i++) {
            int ty = ty0 + i * 8;
            Wt[(ko + ty) * D + oo + tx] = stage[tx][ty];
        }
        __syncthreads();
    }
}

__device__ __forceinline__ void gemm_core(const float* hs, const float* Wt,
                                          int wid, int lane, unsigned long long acc[16][2]) {
    int o4 = lane << 2;
    #pragma unroll
    for (int r = 0; r < 16; r++) { acc[r][0] = 0ull; acc[r][1] = 0ull; }
    for (int k4 = 0; k4 < 32; k4++) {
        unsigned long long wp[4][2];
        #pragma unroll
        for (int kk = 0; kk < 4; kk++) {
            float4 wv = *(const float4*)&Wt[(k4 * 4 + kk) * D + o4];
            wp[kk][0] = pack2(wv.x, wv.y);
            wp[kk][1] = pack2(wv.z, wv.w);
        }
        #pragma unroll
        for (int r = 0; r < 16; r++) {
            float4 h4 = *(const float4*)&hs[(wid * 16 + r) * D + k4 * 4];
            unsigned long long hp;
            hp = dup2(h4.x); fma2(acc[r][0], hp, wp[0][0]); fma2(acc[r][1], hp, wp[0][1]);
            hp = dup2(h4.y); fma2(acc[r][0], hp, wp[1][0]); fma2(acc[r][1], hp, wp[1][1]);
            hp = dup2(h4.z); fma2(acc[r][0], hp, wp[2][0]); fma2(acc[r][1], hp, wp[2][1]);
            hp = dup2(h4.w); fma2(acc[r][0], hp, wp[3][0]); fma2(acc[r][1], hp, wp[3][1]);
        }
    }
}

extern __shared__ float dsm[];
__global__ __launch_bounds__(256, 1)
void k_epilogue(const float4* __restrict__ X, const float4* __restrict__ a4,
                const int* __restrict__ mom,
                const float* __restrict__ W1, const float* __restrict__ b1,
                const float* __restrict__ W2, const float* __restrict__ b2,
                float* __restrict__ out, int N) {
    float* Wt = dsm;            // 16384 floats
    float* hs = dsm + 16384;    // 16384 floats (128 rows x 128)
    __shared__ float stage[32][33];

    int tid = threadIdx.x, wid = tid >> 5, lane = tid & 31;
    int row0 = blockIdx.x * 128;
    float4* hs4 = (float4*)hs;

    float4 aX = a4[lane];
    float4 aH = a4[32 + lane];
    int mi = mom[0];
    bool is1 = (mi == 1) || (__int_as_float(mi) == 1.0f);
    float mf = 1.0f;
    if (!is1) mf = (mi > 0 && mi < 64) ? (float)mi : __int_as_float(mi);

    // Phase A: attention, one warp per node, 16 nodes per warp -> hs
    for (int r = 0; r < 16; r++) {
        int n = row0 + wid * 16 + r;
        float4 o = make_float4(0.f, 0.f, 0.f, 0.f);
        if (n < N) {
            int base = n * 32 + lane;
            float4 xr = X[base];
            float eX = wsum(rlu(xr.x)*aX.x + rlu(xr.y)*aX.y + rlu(xr.z)*aX.z + rlu(xr.w)*aX.w);

            float4 h[6];
            h[0] = lrelu4(g_x1[base]);
            h[1] = lrelu4(g_x2[base]);
            h[2] = lrelu4(g_x3[base]);
            float4 p1 = g_s1[base], p2 = g_s2[base], p3 = g_s3[base], p4 = g_s4[base];
            h[3] = make_float4(apw(p1.x-p2.x,is1,mf), apw(p1.y-p2.y,is1,mf), apw(p1.z-p2.z,is1,mf), apw(p1.w-p2.w,is1,mf));
            h[4] = make_float4(apw(p2.x-p3.x,is1,mf), apw(p2.y-p3.y,is1,mf), apw(p2.z-p3.z,is1,mf), apw(p2.w-p3.w,is1,mf));
            h[5] = make_float4(apw(p3.x-p4.x,is1,mf), apw(p3.y-p4.y,is1,mf), apw(p3.z-p4.z,is1,mf), apw(p3.w-p4.w,is1,mf));

            float e[6];
            #pragma unroll
            for (int c = 0; c < 6; c++) {
                float part = rlu(h[c].x)*aH.x + rlu(h[c].y)*aH.y + rlu(h[c].z)*aH.z + rlu(h[c].w)*aH.w;
                e[c] = eX + wsum(part);
            }
            float mx = e[0];
            #pragma unroll
            for (int c = 1; c < 6; c++) mx = fmaxf(mx, e[c]);
            float at[6], s = 0.f;
            #pragma unroll
            for (int c = 0; c < 6; c++) { at[c] = __expf(e[c] - mx); s += at[c]; }
            float inv = 1.0f / (6.0f * s);
            #pragma unroll
            for (int c = 0; c < 6; c++) {
                o.x += at[c]*h[c].x; o.y += at[c]*h[c].y; o.z += at[c]*h[c].z; o.w += at[c]*h[c].w;
            }
            o.x *= inv; o.y *= inv; o.z *= inv; o.w *= inv;
        }
        hs4[(wid * 16 + r) * 32 + lane] = o;
    }
    __syncthreads();

    // Phase B: GEMM1 (hs @ W1^T + b1, lrelu) -> hs in place
    wtrans(W1, Wt, stage, tid);
    unsigned long long acc[16][2];
    gemm_core(hs, Wt, wid, lane, acc);
    __syncthreads();   // all reads of hs and Wt complete
    {
        int o4 = lane << 2;
        float4 bb = *(const float4*)&b1[o4];
        #pragma unroll
        for (int r = 0; r < 16; r++) {
            float2 lo = unpack2(acc[r][0]);
            float2 hi = unpack2(acc[r][1]);
            float4 o;
            o.x = lrelu(lo.x + bb.x);
            o.y = lrelu(lo.y + bb.y);
            o.z = lrelu(hi.x + bb.z);
            o.w = lrelu(hi.y + bb.w);
            *(float4*)&hs[(wid * 16 + r) * D + o4] = o;
        }
    }
    __syncthreads();

    // Phase C: GEMM2 (hs @ W2^T + b2, lrelu) -> gmem
    wtrans(W2, Wt, stage, tid);
    gemm_core(hs, Wt, wid, lane, acc);
    {
        int o4 = lane << 2;
        float4 bb = *(const float4*)&b2[o4];
        #pragma unroll
        for (int r = 0; r < 16; r++) {
            int rr = row0 + wid * 16 + r;
            if (rr < N) {
                float2 lo = unpack2(acc[r][0]);
                float2 hi = unpack2(acc[r][1]);
                float4 o;
                o.x = lrelu(lo.x + bb.x);
                o.y = lrelu(lo.y + bb.y);
                o.z = lrelu(hi.x + bb.z);
                o.w = lrelu(hi.y + bb.w);
                *(float4*)&out[(size_t)rr * D + o4] = o;
            }
        }
    }
}

// ---------------- launch ----------------
extern "C" void kernel_launch(void* const* d_in, const int* in_sizes, int n_in,
                              void* d_out, int out_size) {
    const float* X   = (const float*)d_in[0];
    const int*   ei  = (const int*)d_in[1];
    const float* ew  = (const float*)d_in[2];
    const float* W1  = (const float*)d_in[3];
    const float* b1  = (const float*)d_in[4];
    const float* W2  = (const float*)d_in[5];
    const float* b2  = (const float*)d_in[6];
    const float* av  = (const float*)d_in[7];
    const int*   mom = (const int*)d_in[8];

    int N = in_sizes[0] / D;
    int E = in_sizes[2];
    const int* row = ei;
    const int* col = ei + E;

    void *p_deg, *p_cnt, *p_cur, *p_x1, *p_x2, *p_x3, *p_s1, *p_s2, *p_s3, *p_s4;
    cudaGetSymbolAddress(&p_deg, g_deg);
    cudaGetSymbolAddress(&p_cnt, g_cnt);
    cudaGetSymbolAddress(&p_cur, g_cur);
    cudaGetSymbolAddress(&p_x1, g_x1);
    cudaGetSymbolAddress(&p_x2, g_x2);
    cudaGetSymbolAddress(&p_x3, g_x3);
    cudaGetSymbolAddress(&p_s1, g_s1);
    cudaGetSymbolAddress(&p_s2, g_s2);
    cudaGetSymbolAddress(&p_s3, g_s3);
    cudaGetSymbolAddress(&p_s4, g_s4);

    cudaMemsetAsync(p_deg, 0, N * sizeof(float), 0);
    cudaMemsetAsync(p_cnt, 0, N * sizeof(int), 0);
    cudaMemsetAsync(p_cur, 0, N * sizeof(int), 0);

    int eb = (E + 255) / 256;
    int nb = (N + 255) / 256;
    int wb = (N * 32 + 255) / 256;
    int sb = (N + 511) / 512;

    k_deg<<<eb, 256>>>(row, col, ew, E);
    k_scale<<<nb, 256>>>(N);
    k_scan1<<<sb, 512>>>(N);
    k_scan2<<<1, 1024>>>(sb, N);
    k_scan3<<<sb, 512>>>(N);
    k_scatter<<<eb, 256>>>(row, col, ew, E);

    k_spmm_first<<<wb, 256>>>((const float4*)X, (float4*)p_x1, (float4*)p_s1, N);
    k_spmm_pair<<<wb, 256>>>((const float4*)p_x1, (const float4*)p_s1,
                             (float4*)p_x2, (float4*)p_s2, N);
    k_spmm_pair<<<wb, 256>>>((const float4*)p_x2, (const float4*)p_s2,
                             (float4*)p_x3, (float4*)p_s3, N);
    k_spmm_sct<<<wb, 256>>>((const float4*)p_s3, (float4*)p_s4, N);

    cudaFuncSetAttribute(k_epilogue, cudaFuncAttributeMaxDynamicSharedMemorySize, 131072);
    int gb = (N + 127) / 128;
    k_epilogue<<<gb, 256, 131072>>>((const float4*)X, (const float4*)av, mom,
                                    W1, b1, W2, b2, (float*)d_out, N);
}